// round 1
// baseline (speedup 1.0000x reference)
#include <cuda_runtime.h>
#include <math.h>

#define N_NODES 8192
#define N_EDGES 65536

// ---------------- scratch (static device globals; no runtime alloc) ----------------
__device__ float g_S   [N_NODES*64];          // up-projected scalars (n,u)
__device__ float g_V   [N_NODES*192];         // up-projected vectors (n, i*64+u)
__device__ float g_EFM [(size_t)N_EDGES*16];  // concat(edge_feats, maginv[sender])
__device__ float g_EDN [N_EDGES];             // per-edge density
__device__ float g_HA  [(size_t)N_EDGES*64];
__device__ float g_HB  [(size_t)N_EDGES*64];
__device__ float g_TP  [(size_t)N_EDGES*320]; // tp_w (e, j*64+u)
__device__ float g_WM  [(size_t)N_EDGES*832]; // wm   (e, j*64+u)
__device__ float g_MS  [N_NODES*320];         // segment-summed mm_s (n, j*64+u)
__device__ float g_MV  [N_NODES*1536];        // segment-summed mm_v (n, i*512 + j*64+u)
__device__ float g_DENS[N_NODES];
__device__ float g_MSP [N_NODES*64];          // post-lin_s
__device__ float g_MVP [N_NODES*192];         // post-lin_v (n, i*64+w)
__device__ float g_CS  [(size_t)N_NODES*640];
__device__ float g_CV  [(size_t)N_NODES*1920];
__device__ int   g_CNT [N_NODES];
__device__ int   g_CUR [N_NODES];
__device__ int   g_OFF [N_NODES+1];
__device__ int   g_SORT[N_EDGES];

// ---------------- generic 64-col tiled GEMM, f32x2 packed FMA ----------------
// C[row, col] = act( alpha * sum_k A[row,k]*B[k,col] )
// grid.x: row tiles of 64 (M must be multiple of 64). grid.y: col tiles of 64 within B.
// A addressed as A[row*ars + k*acs]; B as B[k*brs + col]; C as C[row*crs + col*ccs].
__global__ void __launch_bounds__(256) gemm64(
    const float* __restrict__ A, int ars, int acs,
    const float* __restrict__ B, int brs,
    float* __restrict__ C, int crs, int ccs,
    int K, float alpha, int act)
{
    __shared__ float a_s[64*68];
    const int tid = threadIdx.x;
    const int w = tid & 63, g = tid >> 6;
    const long row0 = (long)blockIdx.x * 64;
    const float* Bt = B + (size_t)blockIdx.y * 64;

    unsigned long long acc[8];
#pragma unroll
    for (int i = 0; i < 8; i++) acc[i] = 0ull;

    for (int k0 = 0; k0 < K; k0 += 64) {
        const int KT = (K - k0) < 64 ? (K - k0) : 64;
        // stage A-tile transposed: a_s[kk][n] (pad 68 avoids heavy bank conflicts)
        for (int i = tid; i < KT * 64; i += 256) {
            int n = i / KT, kk = i - n * KT;
            a_s[kk * 68 + n] = A[(row0 + n) * (long)ars + (long)(k0 + kk) * acs];
        }
        __syncthreads();
        const float* ap = a_s + g * 16;
        for (int kk = 0; kk < KT; kk++) {
            float b = Bt[(size_t)(k0 + kk) * brs + w];
            unsigned int bu = __float_as_uint(b);
            unsigned long long bb = ((unsigned long long)bu << 32) | bu;
            const ulonglong2* av = (const ulonglong2*)(ap + kk * 68);
#pragma unroll
            for (int q = 0; q < 4; q++) {
                ulonglong2 a2 = av[q];
                asm("fma.rn.f32x2 %0, %1, %2, %0;" : "+l"(acc[2*q])   : "l"(a2.x), "l"(bb));
                asm("fma.rn.f32x2 %0, %1, %2, %0;" : "+l"(acc[2*q+1]) : "l"(a2.y), "l"(bb));
            }
        }
        __syncthreads();
    }
    const long col = (long)blockIdx.y * 64 + w;
    const long cbase = (row0 + g * 16) * (long)crs + col * (long)ccs;
#pragma unroll
    for (int i = 0; i < 8; i++) {
        float v0 = __uint_as_float((unsigned int)acc[i]) * alpha;
        float v1 = __uint_as_float((unsigned int)(acc[i] >> 32)) * alpha;
        if (act) {
            v0 = v0 / (1.f + __expf(-v0));
            v1 = v1 / (1.f + __expf(-v1));
        }
        C[cbase + (long)(2*i)   * crs] = v0;
        C[cbase + (long)(2*i+1) * crs] = v1;
    }
}

// ---------------- efm build ----------------
__global__ void k_efm(const float* __restrict__ EF, const float* __restrict__ MI,
                      const int* __restrict__ EI)
{
    int idx = blockIdx.x * 256 + threadIdx.x;     // E*16 threads
    int e = idx >> 4, k = idx & 15;
    float v;
    if (k < 8) v = EF[e * 8 + k];
    else       v = MI[(size_t)EI[e] * 8 + (k - 8)];
    g_EFM[idx] = v;
}

// ---------------- per-edge density ----------------
__global__ void k_dens(const float* __restrict__ EF, const float* __restrict__ DW)
{
    int e = blockIdx.x * 256 + threadIdx.x;       // E threads
    float d = 0.f;
#pragma unroll
    for (int i = 0; i < 8; i++) d += EF[e * 8 + i] * DW[i];
    d *= 0.3535533905932738f;                     // 1/sqrt(8)
    g_EDN[e] = tanhf(d * d);
}

// ---------------- counting sort by receiver ----------------
__global__ void k_zero()
{
    int i = blockIdx.x * 256 + threadIdx.x;
    if (i < N_NODES) { g_CNT[i] = 0; g_CUR[i] = 0; }
}
__global__ void k_hist(const int* __restrict__ EI)
{
    int e = blockIdx.x * 256 + threadIdx.x;
    atomicAdd(&g_CNT[EI[N_EDGES + e]], 1);
}
__global__ void k_scan()
{
    __shared__ int part[1024];
    int t = threadIdx.x;
    int loc[8]; int s = 0;
#pragma unroll
    for (int j = 0; j < 8; j++) { loc[j] = s; s += g_CNT[t * 8 + j]; }
    part[t] = s;
    __syncthreads();
    for (int off = 1; off < 1024; off <<= 1) {
        int v = (t >= off) ? part[t - off] : 0;
        __syncthreads();
        part[t] += v;
        __syncthreads();
    }
    int excl = part[t] - s;
#pragma unroll
    for (int j = 0; j < 8; j++) g_OFF[t * 8 + j] = excl + loc[j];
    if (t == 1023) g_OFF[N_NODES] = part[1023];
}
__global__ void k_scatter(const int* __restrict__ EI)
{
    int e = blockIdx.x * 256 + threadIdx.x;
    int r = EI[N_EDGES + e];
    int p = g_OFF[r] + atomicAdd(&g_CUR[r], 1);
    g_SORT[p] = e;
}

// ---------------- per-node edge combine + segment reduction (no atomics) ----------------
__global__ void __launch_bounds__(64) k_mm(const float* __restrict__ EA,
                                           const float* __restrict__ MA,
                                           const int* __restrict__ EI)
{
    const int n = blockIdx.x;
    const int u = threadIdx.x;
    const int beg = g_OFF[n], end = g_OFF[n + 1];

    float as0 = 0, as1 = 0, as2 = 0, as3 = 0, as4 = 0;
    float av[8][3];
#pragma unroll
    for (int j = 0; j < 8; j++)
#pragma unroll
        for (int i = 0; i < 3; i++) av[j][i] = 0.f;
    float dens = 0.f;

    const float I3 = 0.5773502691896258f;   // 1/sqrt(3)
    const float I2 = 0.7071067811865476f;   // 1/sqrt(2)

    for (int q = beg; q < end; q++) {
        const int e = g_SORT[q];
        const int snd = EI[e];
        const float* ea = EA + (size_t)e * 4;
        const float y0 = ea[0], yx = ea[1], yy = ea[2], yz = ea[3];
        const float* ma = MA + (size_t)snd * 4;
        const float m0 = ma[0], mx = ma[1], my = ma[2], mz = ma[3];
        const float xs = g_S[(size_t)snd * 64 + u];
        const float* vp = g_V + (size_t)snd * 192 + u;
        const float vx = vp[0], vy = vp[64], vz = vp[128];
        const float* tp = g_TP + (size_t)e * 320 + u;
        const float t0 = tp[0], t1 = tp[64], t2 = tp[128], t3 = tp[192], t4 = tp[256];
        const float* wm = g_WM + (size_t)e * 832 + u;

        // message tensor products
        const float ms0 = t0 * xs * y0;
        const float A0x = t1 * xs * yx, A0y = t1 * xs * yy, A0z = t1 * xs * yz; // m_v0
        const float B0x = t2 * vx * y0, B0y = t2 * vy * y0, B0z = t2 * vz * y0; // m_v1
        const float ms1 = t3 * (vx * yx + vy * yy + vz * yz) * I3;              // m_s1
        const float cx = vy * yz - vz * yy;
        const float cy = vz * yx - vx * yz;
        const float cz = vx * yy - vy * yx;
        const float C0x = t4 * cx * I2, C0y = t4 * cy * I2, C0z = t4 * cz * I2; // m_v2

        // magnetic combine (13 weights)
        as0 += wm[0] * ms0 * m0;
        { float w_ = wm[64] * ms0;  av[0][0] += w_ * mx; av[0][1] += w_ * my; av[0][2] += w_ * mz; }
        as1 += wm[128] * ms1 * m0;
        { float w_ = wm[192] * ms1; av[1][0] += w_ * mx; av[1][1] += w_ * my; av[1][2] += w_ * mz; }

        { float w_ = wm[256] * m0;  av[2][0] += w_ * A0x; av[2][1] += w_ * A0y; av[2][2] += w_ * A0z; }
        as2 += wm[320] * (A0x * mx + A0y * my + A0z * mz) * I3;
        { float w_ = wm[384] * I2;
          av[3][0] += w_ * (A0y * mz - A0z * my);
          av[3][1] += w_ * (A0z * mx - A0x * mz);
          av[3][2] += w_ * (A0x * my - A0y * mx); }

        { float w_ = wm[448] * m0;  av[4][0] += w_ * B0x; av[4][1] += w_ * B0y; av[4][2] += w_ * B0z; }
        as3 += wm[512] * (B0x * mx + B0y * my + B0z * mz) * I3;
        { float w_ = wm[576] * I2;
          av[5][0] += w_ * (B0y * mz - B0z * my);
          av[5][1] += w_ * (B0z * mx - B0x * mz);
          av[5][2] += w_ * (B0x * my - B0y * mx); }

        { float w_ = wm[640] * m0;  av[6][0] += w_ * C0x; av[6][1] += w_ * C0y; av[6][2] += w_ * C0z; }
        as4 += wm[704] * (C0x * mx + C0y * my + C0z * mz) * I3;
        { float w_ = wm[768] * I2;
          av[7][0] += w_ * (C0y * mz - C0z * my);
          av[7][1] += w_ * (C0z * mx - C0x * mz);
          av[7][2] += w_ * (C0x * my - C0y * mx); }

        dens += g_EDN[e];
    }

    const size_t b = (size_t)n * 320 + u;
    g_MS[b]       = as0;
    g_MS[b + 64]  = as1;
    g_MS[b + 128] = as2;
    g_MS[b + 192] = as3;
    g_MS[b + 256] = as4;
    const size_t bv = (size_t)n * 1536 + u;
#pragma unroll
    for (int i = 0; i < 3; i++)
#pragma unroll
        for (int j = 0; j < 8; j++)
            g_MV[bv + i * 512 + j * 64] = av[j][i];
    if (u == 0) g_DENS[n] = dens;
}

// ---------------- skip-einsum coefficient build (density division folded here) ----------------
__global__ void k_coef(const float* __restrict__ attrs)
{
    int idx = blockIdx.x * 256 + threadIdx.x;     // N*640 threads
    int n = idx / 640, k = idx - n * 640;
    int u = k / 10, v = k - u * 10;
    float sc = attrs[n * 10 + v] / (g_DENS[n] + 1.f);
    g_CS[idx] = g_MSP[n * 64 + u] * sc;
#pragma unroll
    for (int i = 0; i < 3; i++)
        g_CV[(size_t)n * 1920 + i * 640 + k] = g_MVP[n * 192 + i * 64 + u] * sc;
}

// ---------------- launcher ----------------
extern "C" void kernel_launch(void* const* d_in, const int* in_sizes, int n_in,
                              void* d_out, int out_size)
{
    (void)in_sizes; (void)n_in; (void)out_size;
    const float* node_attrs = (const float*)d_in[0];
    const float* node_feats = (const float*)d_in[1];
    const float* edge_attrs = (const float*)d_in[2];
    const float* edge_feats = (const float*)d_in[3];
    const int*   edge_index = (const int*)  d_in[4];
    const float* maginv     = (const float*)d_in[5];
    const float* magattr    = (const float*)d_in[6];
    const float* Wups       = (const float*)d_in[7];
    const float* Wupv       = (const float*)d_in[8];
    const float* w0         = (const float*)d_in[9];
    const float* w1         = (const float*)d_in[10];
    const float* w2         = (const float*)d_in[11];
    const float* w3         = (const float*)d_in[12];
    const float* magw       = (const float*)d_in[13];
    const float* densw      = (const float*)d_in[14];
    const float* lins       = (const float*)d_in[15];
    const float* linv       = (const float*)d_in[16];
    const float* skips      = (const float*)d_in[17];
    const float* skipv      = (const float*)d_in[18];
    float* out = (float*)d_out;

    float *pS, *pV, *pEFM, *pHA, *pHB, *pTP, *pWM, *pMS, *pMV, *pMSP, *pMVP, *pCS, *pCV;
    cudaGetSymbolAddress((void**)&pS,   g_S);
    cudaGetSymbolAddress((void**)&pV,   g_V);
    cudaGetSymbolAddress((void**)&pEFM, g_EFM);
    cudaGetSymbolAddress((void**)&pHA,  g_HA);
    cudaGetSymbolAddress((void**)&pHB,  g_HB);
    cudaGetSymbolAddress((void**)&pTP,  g_TP);
    cudaGetSymbolAddress((void**)&pWM,  g_WM);
    cudaGetSymbolAddress((void**)&pMS,  g_MS);
    cudaGetSymbolAddress((void**)&pMV,  g_MV);
    cudaGetSymbolAddress((void**)&pMSP, g_MSP);
    cudaGetSymbolAddress((void**)&pMVP, g_MVP);
    cudaGetSymbolAddress((void**)&pCS,  g_CS);
    cudaGetSymbolAddress((void**)&pCV,  g_CV);

    const float a8   = 0.125f;                  // 1/sqrt(64)
    const float a4   = 0.25f;                   // 1/sqrt(16)
    const float a320 = 1.f / sqrtf(320.f);
    const float a512 = 1.f / sqrtf(512.f);
    const float a640 = 1.f / sqrtf(640.f);      // 1/fan

    // node up-projection
    gemm64<<<dim3(N_NODES/64, 1), 256>>>(node_feats, 256, 1, Wups, 64, pS, 64, 1, 64, a8, 0);
    for (int i = 0; i < 3; i++)
        gemm64<<<dim3(N_NODES/64, 1), 256>>>(node_feats + 64 + i, 256, 3, Wupv, 64,
                                             pV + i * 64, 192, 1, 64, a8, 0);

    // edge feature concat + density
    k_efm <<<N_EDGES*16/256, 256>>>(edge_feats, maginv, edge_index);
    k_dens<<<N_EDGES/256,    256>>>(edge_feats, densw);

    // edge MLP + mag projection (the big GEMMs)
    gemm64<<<dim3(N_EDGES/64, 1),  256>>>(pEFM, 16, 1, w0,   64,  pHA, 64,  1, 16, a4, 1);
    gemm64<<<dim3(N_EDGES/64, 1),  256>>>(pHA,  64, 1, w1,   64,  pHB, 64,  1, 64, a8, 1);
    gemm64<<<dim3(N_EDGES/64, 1),  256>>>(pHB,  64, 1, w2,   64,  pHA, 64,  1, 64, a8, 1);
    gemm64<<<dim3(N_EDGES/64, 5),  256>>>(pHA,  64, 1, w3,   320, pTP, 320, 1, 64, a8, 0);
    gemm64<<<dim3(N_EDGES/64, 13), 256>>>(pEFM, 16, 1, magw, 832, pWM, 832, 1, 16, a4, 0);

    // counting sort of edges by receiver
    k_zero   <<<N_NODES/256, 256>>>();
    k_hist   <<<N_EDGES/256, 256>>>(edge_index);
    k_scan   <<<1, 1024>>>();
    k_scatter<<<N_EDGES/256, 256>>>(edge_index);

    // per-node tensor-product combine + segment reduction
    k_mm<<<N_NODES, 64>>>(edge_attrs, magattr, edge_index);

    // lin_s / lin_v
    gemm64<<<dim3(N_NODES/64, 1), 256>>>(pMS, 320, 1, lins, 64, pMSP, 64, 1, 320, a320, 0);
    for (int i = 0; i < 3; i++)
        gemm64<<<dim3(N_NODES/64, 1), 256>>>(pMV + i * 512, 1536, 1, linv, 64,
                                             pMVP + i * 64, 192, 1, 512, a512, 0);

    // skip einsum as GEMMs via coefficient matrices
    k_coef<<<N_NODES*640/256, 256>>>(node_attrs);
    gemm64<<<dim3(N_NODES/64, 1), 256>>>(pCS, 640, 1, skips, 64, out, 256, 4, 640, a640, 0);
    for (int i = 0; i < 3; i++)
        gemm64<<<dim3(N_NODES/64, 1), 256>>>(pCV + i * 640, 1920, 1, skipv, 64,
                                             out + 1 + i, 256, 4, 640, a640, 0);
}

// round 2
// speedup vs baseline: 1.7684x; 1.7684x over previous
#include <cuda_runtime.h>
#include <math.h>

#define N_NODES 8192
#define N_EDGES 65536

typedef unsigned long long ull;

// ---------------- scratch (static device globals; no runtime alloc) ----------------
__device__ float g_S   [N_NODES*64];          // up-projected scalars (n,u)
__device__ float g_V   [N_NODES*192];         // up-projected vectors (n, i*64+u)
__device__ float g_EFM [(size_t)N_EDGES*16];  // concat(edge_feats, maginv[sender])
__device__ float g_EDN [N_EDGES];             // per-edge density
__device__ float g_HA  [(size_t)N_EDGES*64];
__device__ float g_HB  [(size_t)N_EDGES*64];
__device__ float g_TP  [(size_t)N_EDGES*320]; // tp_w (e, j*64+u)
__device__ float g_WM  [(size_t)N_EDGES*832]; // wm   (e, j*64+u)
__device__ float g_MS  [N_NODES*320];         // segment-summed mm_s (n, j*64+u)
__device__ float g_MV  [N_NODES*1536];        // segment-summed mm_v (n, i*512 + j*64+u)
__device__ float g_DENS[N_NODES];
__device__ float g_MSP [N_NODES*64];          // post-lin_s
__device__ float g_MVP [N_NODES*192];         // post-lin_v (n, i*64+w)
__device__ float g_C   [(size_t)N_NODES*2560];// skip coefs (n, j(=s,vx,vy,vz), 640)
__device__ int   g_CNT [N_NODES];
__device__ int   g_CUR [N_NODES];
__device__ int   g_OFF [N_NODES+1];
__device__ int   g_SORT[N_EDGES];

__device__ __forceinline__ ull bcast(float f) {
    unsigned int u = __float_as_uint(f);
    return ((ull)u << 32) | u;
}
__device__ __forceinline__ void fma2(ull& acc, ull a, ull b) {
    asm("fma.rn.f32x2 %0, %1, %2, %0;" : "+l"(acc) : "l"(a), "l"(b));
}

// ---------------- register-blocked GEMM: 128 rows x 64 cols per block, 256 thr ----
// C[row, col, z] = act( alpha * sum_k A[z][row,k] * B[z][k,col] )
// A addressed: (A + z*azs)[row*ars + k*acs]
// B: z==0 -> B0, z>0 -> Bz;  B[k*brs + col0 + c]
// C addressed: (C + z*czs)[row*crs + col*ccs]
__global__ void __launch_bounds__(256) gemm128(
    const float* __restrict__ A, long ars, int acs, long azs,
    const float* __restrict__ B0, const float* __restrict__ Bz, int brs,
    float* __restrict__ C, long crs, int ccs, long czs,
    int K, float alpha, int act)
{
    __shared__ float As[32*132];   // [kk][row], padded
    __shared__ float Bs[32*68];    // [kk][col], padded

    const int tid = threadIdx.x;
    const int tx = tid & 15;       // col group: cols tx*4 .. tx*4+3
    const int ty = tid >> 4;       // row group: rows ty*8 .. ty*8+7
    const long row0 = (long)blockIdx.x * 128;
    const int  col0 = blockIdx.y * 64;
    const int  z = blockIdx.z;
    A += (long)z * azs;
    C += (long)z * czs;
    const float* __restrict__ B = (z == 0) ? B0 : Bz;

    ull acc[16];
#pragma unroll
    for (int i = 0; i < 16; i++) acc[i] = 0ull;

    for (int k0 = 0; k0 < K; k0 += 32) {
        // stage A tile transposed (zero-fill beyond K)
#pragma unroll 4
        for (int i = tid; i < 32 * 128; i += 256) {
            int kk = i >> 7, n = i & 127;
            float v = 0.f;
            if (k0 + kk < K) v = A[(row0 + n) * ars + (long)(k0 + kk) * acs];
            As[kk * 132 + n] = v;
        }
        // stage B tile
#pragma unroll 4
        for (int i = tid; i < 32 * 64; i += 256) {
            int kk = i >> 6, c = i & 63;
            float v = 0.f;
            if (k0 + kk < K) v = B[(long)(k0 + kk) * brs + col0 + c];
            Bs[kk * 68 + c] = v;
        }
        __syncthreads();

#pragma unroll
        for (int kk = 0; kk < 32; kk++) {
            const ulonglong2* ap = (const ulonglong2*)(As + kk * 132 + ty * 8);
            ulonglong2 a01 = ap[0];               // rows 0-1, 2-3 (packed pairs)
            ulonglong2 a23 = ap[1];               // rows 4-5, 6-7
            const float4 bv = *(const float4*)(Bs + kk * 68 + tx * 4);
            ull b0 = bcast(bv.x), b1 = bcast(bv.y), b2 = bcast(bv.z), b3 = bcast(bv.w);
            fma2(acc[0],  a01.x, b0); fma2(acc[1],  a01.x, b1);
            fma2(acc[2],  a01.x, b2); fma2(acc[3],  a01.x, b3);
            fma2(acc[4],  a01.y, b0); fma2(acc[5],  a01.y, b1);
            fma2(acc[6],  a01.y, b2); fma2(acc[7],  a01.y, b3);
            fma2(acc[8],  a23.x, b0); fma2(acc[9],  a23.x, b1);
            fma2(acc[10], a23.x, b2); fma2(acc[11], a23.x, b3);
            fma2(acc[12], a23.y, b0); fma2(acc[13], a23.y, b1);
            fma2(acc[14], a23.y, b2); fma2(acc[15], a23.y, b3);
        }
        __syncthreads();
    }

    // write out 8 rows x 4 cols
#pragma unroll
    for (int rp = 0; rp < 4; rp++) {
        long r = row0 + ty * 8 + rp * 2;
#pragma unroll
        for (int c = 0; c < 4; c++) {
            ull av = acc[rp * 4 + c];
            float v0 = __uint_as_float((unsigned int)av) * alpha;
            float v1 = __uint_as_float((unsigned int)(av >> 32)) * alpha;
            if (act) {
                v0 = v0 / (1.f + __expf(-v0));
                v1 = v1 / (1.f + __expf(-v1));
            }
            long col = (long)(col0 + tx * 4 + c) * ccs;
            C[r * crs + col] = v0;
            C[(r + 1) * crs + col] = v1;
        }
    }
}

// ---------------- efm build ----------------
__global__ void k_efm(const float* __restrict__ EF, const float* __restrict__ MI,
                      const int* __restrict__ EI)
{
    int idx = blockIdx.x * 256 + threadIdx.x;     // E*16 threads
    int e = idx >> 4, k = idx & 15;
    float v;
    if (k < 8) v = EF[e * 8 + k];
    else       v = MI[(size_t)EI[e] * 8 + (k - 8)];
    g_EFM[idx] = v;
}

// ---------------- per-edge density ----------------
__global__ void k_dens(const float* __restrict__ EF, const float* __restrict__ DW)
{
    int e = blockIdx.x * 256 + threadIdx.x;       // E threads
    float d = 0.f;
#pragma unroll
    for (int i = 0; i < 8; i++) d += EF[e * 8 + i] * DW[i];
    d *= 0.3535533905932738f;                     // 1/sqrt(8)
    g_EDN[e] = tanhf(d * d);
}

// ---------------- counting sort by receiver ----------------
__global__ void k_zero()
{
    int i = blockIdx.x * 256 + threadIdx.x;
    if (i < N_NODES) { g_CNT[i] = 0; g_CUR[i] = 0; }
}
__global__ void k_hist(const int* __restrict__ EI)
{
    int e = blockIdx.x * 256 + threadIdx.x;
    atomicAdd(&g_CNT[EI[N_EDGES + e]], 1);
}
__global__ void k_scan()
{
    __shared__ int part[1024];
    int t = threadIdx.x;
    int loc[8]; int s = 0;
#pragma unroll
    for (int j = 0; j < 8; j++) { loc[j] = s; s += g_CNT[t * 8 + j]; }
    part[t] = s;
    __syncthreads();
    for (int off = 1; off < 1024; off <<= 1) {
        int v = (t >= off) ? part[t - off] : 0;
        __syncthreads();
        part[t] += v;
        __syncthreads();
    }
    int excl = part[t] - s;
#pragma unroll
    for (int j = 0; j < 8; j++) g_OFF[t * 8 + j] = excl + loc[j];
    if (t == 1023) g_OFF[N_NODES] = part[1023];
}
__global__ void k_scatter(const int* __restrict__ EI)
{
    int e = blockIdx.x * 256 + threadIdx.x;
    int r = EI[N_EDGES + e];
    int p = g_OFF[r] + atomicAdd(&g_CUR[r], 1);
    g_SORT[p] = e;
}

// ---------------- per-node edge combine + segment reduction (no atomics) ----------------
__global__ void __launch_bounds__(64) k_mm(const float* __restrict__ EA,
                                           const float* __restrict__ MA,
                                           const int* __restrict__ EI)
{
    const int n = blockIdx.x;
    const int u = threadIdx.x;
    const int beg = g_OFF[n], end = g_OFF[n + 1];

    float as0 = 0, as1 = 0, as2 = 0, as3 = 0, as4 = 0;
    float av[8][3];
#pragma unroll
    for (int j = 0; j < 8; j++)
#pragma unroll
        for (int i = 0; i < 3; i++) av[j][i] = 0.f;
    float dens = 0.f;

    const float I3 = 0.5773502691896258f;   // 1/sqrt(3)
    const float I2 = 0.7071067811865476f;   // 1/sqrt(2)

    for (int q = beg; q < end; q++) {
        const int e = g_SORT[q];
        const int snd = EI[e];
        const float* ea = EA + (size_t)e * 4;
        const float y0 = ea[0], yx = ea[1], yy = ea[2], yz = ea[3];
        const float* ma = MA + (size_t)snd * 4;
        const float m0 = ma[0], mx = ma[1], my = ma[2], mz = ma[3];
        const float xs = g_S[(size_t)snd * 64 + u];
        const float* vp = g_V + (size_t)snd * 192 + u;
        const float vx = vp[0], vy = vp[64], vz = vp[128];
        const float* tp = g_TP + (size_t)e * 320 + u;
        const float t0 = tp[0], t1 = tp[64], t2 = tp[128], t3 = tp[192], t4 = tp[256];
        const float* wm = g_WM + (size_t)e * 832 + u;

        // message tensor products
        const float ms0 = t0 * xs * y0;
        const float A0x = t1 * xs * yx, A0y = t1 * xs * yy, A0z = t1 * xs * yz; // m_v0
        const float B0x = t2 * vx * y0, B0y = t2 * vy * y0, B0z = t2 * vz * y0; // m_v1
        const float ms1 = t3 * (vx * yx + vy * yy + vz * yz) * I3;              // m_s1
        const float cx = vy * yz - vz * yy;
        const float cy = vz * yx - vx * yz;
        const float cz = vx * yy - vy * yx;
        const float C0x = t4 * cx * I2, C0y = t4 * cy * I2, C0z = t4 * cz * I2; // m_v2

        // magnetic combine (13 weights)
        as0 += wm[0] * ms0 * m0;
        { float w_ = wm[64] * ms0;  av[0][0] += w_ * mx; av[0][1] += w_ * my; av[0][2] += w_ * mz; }
        as1 += wm[128] * ms1 * m0;
        { float w_ = wm[192] * ms1; av[1][0] += w_ * mx; av[1][1] += w_ * my; av[1][2] += w_ * mz; }

        { float w_ = wm[256] * m0;  av[2][0] += w_ * A0x; av[2][1] += w_ * A0y; av[2][2] += w_ * A0z; }
        as2 += wm[320] * (A0x * mx + A0y * my + A0z * mz) * I3;
        { float w_ = wm[384] * I2;
          av[3][0] += w_ * (A0y * mz - A0z * my);
          av[3][1] += w_ * (A0z * mx - A0x * mz);
          av[3][2] += w_ * (A0x * my - A0y * mx); }

        { float w_ = wm[448] * m0;  av[4][0] += w_ * B0x; av[4][1] += w_ * B0y; av[4][2] += w_ * B0z; }
        as3 += wm[512] * (B0x * mx + B0y * my + B0z * mz) * I3;
        { float w_ = wm[576] * I2;
          av[5][0] += w_ * (B0y * mz - B0z * my);
          av[5][1] += w_ * (B0z * mx - B0x * mz);
          av[5][2] += w_ * (B0x * my - B0y * mx); }

        { float w_ = wm[640] * m0;  av[6][0] += w_ * C0x; av[6][1] += w_ * C0y; av[6][2] += w_ * C0z; }
        as4 += wm[704] * (C0x * mx + C0y * my + C0z * mz) * I3;
        { float w_ = wm[768] * I2;
          av[7][0] += w_ * (C0y * mz - C0z * my);
          av[7][1] += w_ * (C0z * mx - C0x * mz);
          av[7][2] += w_ * (C0x * my - C0y * mx); }

        dens += g_EDN[e];
    }

    const size_t b = (size_t)n * 320 + u;
    g_MS[b]       = as0;
    g_MS[b + 64]  = as1;
    g_MS[b + 128] = as2;
    g_MS[b + 192] = as3;
    g_MS[b + 256] = as4;
    const size_t bv = (size_t)n * 1536 + u;
#pragma unroll
    for (int i = 0; i < 3; i++)
#pragma unroll
        for (int j = 0; j < 8; j++)
            g_MV[bv + i * 512 + j * 64] = av[j][i];
    if (u == 0) g_DENS[n] = dens;
}

// ---------------- skip-einsum coefficient build (density division folded here) ----------------
__global__ void k_coef(const float* __restrict__ attrs)
{
    int idx = blockIdx.x * 256 + threadIdx.x;     // N*640 threads
    int n = idx / 640, k = idx - n * 640;
    int u = k / 10, v = k - u * 10;
    float sc = attrs[n * 10 + v] / (g_DENS[n] + 1.f);
    size_t base = (size_t)n * 2560 + k;
    g_C[base] = g_MSP[n * 64 + u] * sc;
#pragma unroll
    for (int i = 0; i < 3; i++)
        g_C[base + (i + 1) * 640] = g_MVP[n * 192 + i * 64 + u] * sc;
}

// ---------------- launcher ----------------
extern "C" void kernel_launch(void* const* d_in, const int* in_sizes, int n_in,
                              void* d_out, int out_size)
{
    (void)in_sizes; (void)n_in; (void)out_size;
    const float* node_attrs = (const float*)d_in[0];
    const float* node_feats = (const float*)d_in[1];
    const float* edge_attrs = (const float*)d_in[2];
    const float* edge_feats = (const float*)d_in[3];
    const int*   edge_index = (const int*)  d_in[4];
    const float* maginv     = (const float*)d_in[5];
    const float* magattr    = (const float*)d_in[6];
    const float* Wups       = (const float*)d_in[7];
    const float* Wupv       = (const float*)d_in[8];
    const float* w0         = (const float*)d_in[9];
    const float* w1         = (const float*)d_in[10];
    const float* w2         = (const float*)d_in[11];
    const float* w3         = (const float*)d_in[12];
    const float* magw       = (const float*)d_in[13];
    const float* densw      = (const float*)d_in[14];
    const float* lins       = (const float*)d_in[15];
    const float* linv       = (const float*)d_in[16];
    const float* skips      = (const float*)d_in[17];
    const float* skipv      = (const float*)d_in[18];
    float* out = (float*)d_out;

    float *pS, *pV, *pEFM, *pHA, *pHB, *pTP, *pWM, *pMS, *pMV, *pMSP, *pMVP, *pC;
    cudaGetSymbolAddress((void**)&pS,   g_S);
    cudaGetSymbolAddress((void**)&pV,   g_V);
    cudaGetSymbolAddress((void**)&pEFM, g_EFM);
    cudaGetSymbolAddress((void**)&pHA,  g_HA);
    cudaGetSymbolAddress((void**)&pHB,  g_HB);
    cudaGetSymbolAddress((void**)&pTP,  g_TP);
    cudaGetSymbolAddress((void**)&pWM,  g_WM);
    cudaGetSymbolAddress((void**)&pMS,  g_MS);
    cudaGetSymbolAddress((void**)&pMV,  g_MV);
    cudaGetSymbolAddress((void**)&pMSP, g_MSP);
    cudaGetSymbolAddress((void**)&pMVP, g_MVP);
    cudaGetSymbolAddress((void**)&pC,   g_C);

    const float a8   = 0.125f;                  // 1/sqrt(64)
    const float a4   = 0.25f;                   // 1/sqrt(16)
    const float a320 = 1.f / sqrtf(320.f);
    const float a512 = 1.f / sqrtf(512.f);
    const float a640 = 1.f / sqrtf(640.f);      // 1/fan

    const int NB = N_NODES / 128;   // 64
    const int EB = N_EDGES / 128;   // 512

    // node up-projection: scalar + 3 vector components (batched in z)
    gemm128<<<dim3(NB, 1, 1), 256>>>(node_feats, 256, 1, 0, Wups, Wups, 64,
                                     pS, 64, 1, 0, 64, a8, 0);
    gemm128<<<dim3(NB, 1, 3), 256>>>(node_feats + 64, 256, 3, 1, Wupv, Wupv, 64,
                                     pV, 192, 1, 64, 64, a8, 0);

    // edge feature concat + density
    k_efm <<<N_EDGES*16/256, 256>>>(edge_feats, maginv, edge_index);
    k_dens<<<N_EDGES/256,    256>>>(edge_feats, densw);

    // edge MLP + mag projection (the big GEMMs)
    gemm128<<<dim3(EB, 1,  1), 256>>>(pEFM, 16, 1, 0, w0,   w0,   64,  pHA, 64,  1, 0, 16, a4, 1);
    gemm128<<<dim3(EB, 1,  1), 256>>>(pHA,  64, 1, 0, w1,   w1,   64,  pHB, 64,  1, 0, 64, a8, 1);
    gemm128<<<dim3(EB, 1,  1), 256>>>(pHB,  64, 1, 0, w2,   w2,   64,  pHA, 64,  1, 0, 64, a8, 1);
    gemm128<<<dim3(EB, 5,  1), 256>>>(pHA,  64, 1, 0, w3,   w3,   320, pTP, 320, 1, 0, 64, a8, 0);
    gemm128<<<dim3(EB, 13, 1), 256>>>(pEFM, 16, 1, 0, magw, magw, 832, pWM, 832, 1, 0, 16, a4, 0);

    // counting sort of edges by receiver
    k_zero   <<<N_NODES/256, 256>>>();
    k_hist   <<<N_EDGES/256, 256>>>(edge_index);
    k_scan   <<<1, 1024>>>();
    k_scatter<<<N_EDGES/256, 256>>>(edge_index);

    // per-node tensor-product combine + segment reduction
    k_mm<<<N_NODES, 64>>>(edge_attrs, magattr, edge_index);

    // lin_s / lin_v (lin_v batched over 3 components)
    gemm128<<<dim3(NB, 1, 1), 256>>>(pMS, 320, 1, 0, lins, lins, 64,
                                     pMSP, 64, 1, 0, 320, a320, 0);
    gemm128<<<dim3(NB, 1, 3), 256>>>(pMV, 1536, 1, 512, linv, linv, 64,
                                     pMVP, 192, 1, 64, 512, a512, 0);

    // skip einsum as one batched GEMM (z=0 scalar w/ skips, z=1..3 vector w/ skipv)
    k_coef<<<N_NODES*640/256, 256>>>(node_attrs);
    gemm128<<<dim3(NB, 1, 4), 256>>>(pC, 2560, 1, 640, skips, skipv, 64,
                                     out, 256, 4, 1, 640, a640, 0);
}

// round 3
// speedup vs baseline: 2.3425x; 1.3247x over previous
#include <cuda_runtime.h>
#include <math.h>

#define N_NODES 8192
#define N_EDGES 65536

typedef unsigned long long ull;

// ---------------- scratch (static device globals; no runtime alloc) ----------------
__device__ float g_S   [N_NODES*64];
__device__ float g_V   [N_NODES*192];
__device__ float g_EFM [(size_t)N_EDGES*16];
__device__ float g_EDN [N_EDGES];
__device__ float g_HA  [(size_t)N_EDGES*64];
__device__ float g_HB  [(size_t)N_EDGES*64];
__device__ float g_TP  [(size_t)N_EDGES*320];
__device__ float g_WM  [(size_t)N_EDGES*832];
__device__ float g_MS  [N_NODES*320];
__device__ float g_MV  [N_NODES*1536];
__device__ float g_AI  [N_NODES*10];          // attrs / (dens+1)
__device__ float g_MSP [N_NODES*64];
__device__ float g_MVP [N_NODES*192];
__device__ int   g_CNT [N_NODES];
__device__ int   g_CUR [N_NODES];
__device__ int   g_OFF [N_NODES+1];
__device__ int   g_SORT[N_EDGES];

__device__ __forceinline__ ull bcast(float f) {
    unsigned int u = __float_as_uint(f);
    ull r;
    asm("mov.b64 %0, {%1, %1};" : "=l"(r) : "r"(u));
    return r;
}
__device__ __forceinline__ void fma2(ull& acc, ull a, ull b) {
    asm("fma.rn.f32x2 %0, %1, %2, %0;" : "+l"(acc) : "l"(a), "l"(b));
}

// ================= register-blocked GEMM =================
// Tile: 128 rows x 64 cols, 128 threads, 8x8 microtile (rows paired in f32x2).
// C[row, col, z] = act( alpha * sum_k A[z][row,k] * B[z][k,col] )
// Normal mode:  A element (n,k) = (A + z*azs)[n*ars + k*acs]
// SKIP mode:    A element (n,k) = msel[n, k/10] * g_AI[n*10 + k%10]
//               where msel = (z==0 ? MSP row stride 64 : MVP+(z-1)*64 row stride 192)
// B: z==0 -> B0, else Bz;  B[k*brs + col]
// C: (C + z*czs)[row*crs + col*ccs]
template<bool SKIP>
__global__ void __launch_bounds__(128) gemmk(
    const float* __restrict__ A, long ars, int acs, long azs,
    const float* __restrict__ B0, const float* __restrict__ Bz, int brs,
    float* __restrict__ C, long crs, int ccs, long czs,
    int K, float alpha, int act,
    const float* __restrict__ MSP, const float* __restrict__ MVP)
{
    const int LDA = 132;
    __shared__ float As[32*132];   // [kk][row]
    __shared__ float Bs[32*68];    // [kk][col]

    const int tid = threadIdx.x;
    const int tx = tid & 7;        // col group (8 cols each)
    const int ty = tid >> 3;       // row group (8 rows each), 0..15
    const long row0 = (long)blockIdx.x * 128;
    const int  col0 = blockIdx.y * 64;
    const int  z = blockIdx.z;
    const float* __restrict__ B = (z == 0) ? B0 : Bz;
    C += (long)z * czs;

    // per-thread A source pointers
    const float* Arow;
    const float* ai = 0;
    if (SKIP) {
        Arow = (z == 0) ? (MSP + (row0 + tid) * 64)
                        : (MVP + (row0 + tid) * 192 + (z - 1) * 64);
        ai = g_AI + (row0 + tid) * 10;
    } else {
        Arow = A + (long)z * azs + (row0 + tid) * ars;
    }

    ull acc[32];
#pragma unroll
    for (int i = 0; i < 32; i++) acc[i] = 0ull;

    for (int k0 = 0; k0 < K; k0 += 32) {
        // ---- stage A (thread tid owns row row0+tid) ----
        if (SKIP) {
#pragma unroll 8
            for (int kk = 0; kk < 32; kk++) {
                int k = k0 + kk;                  // K=640 exact -> no guard
                int u = (k * 6554) >> 16;
                int v = k - u * 10;
                As[kk * LDA + tid] = Arow[u] * ai[v];
            }
        } else if (acs == 1) {
#pragma unroll
            for (int c = 0; c < 8; c++) {
                float4 val = make_float4(0.f, 0.f, 0.f, 0.f);
                if (k0 + c * 4 < K)
                    val = *(const float4*)(Arow + k0 + c * 4);
                As[(c * 4 + 0) * LDA + tid] = val.x;
                As[(c * 4 + 1) * LDA + tid] = val.y;
                As[(c * 4 + 2) * LDA + tid] = val.z;
                As[(c * 4 + 3) * LDA + tid] = val.w;
            }
        } else {
#pragma unroll 8
            for (int kk = 0; kk < 32; kk++) {
                float v = 0.f;
                if (k0 + kk < K) v = Arow[(long)(k0 + kk) * acs];
                As[kk * LDA + tid] = v;
            }
        }
        // ---- stage B ----
#pragma unroll
        for (int j = 0; j < 4; j++) {
            int kk = (tid >> 4) + j * 8;
            int c  = (tid & 15) * 4;
            float4 val = make_float4(0.f, 0.f, 0.f, 0.f);
            if (k0 + kk < K)
                val = *(const float4*)(B + (size_t)(k0 + kk) * brs + col0 + c);
            *(float4*)(Bs + kk * 68 + c) = val;
        }
        __syncthreads();

#pragma unroll 8
        for (int kk = 0; kk < 32; kk++) {
            const ulonglong2* ap = (const ulonglong2*)(As + kk * LDA + ty * 8);
            ulonglong2 aA = ap[0];    // row pairs 0-1, 2-3
            ulonglong2 aB = ap[1];    // row pairs 4-5, 6-7
            const float4* bp = (const float4*)(Bs + kk * 68 + tx * 8);
            float4 b0 = bp[0], b1 = bp[1];
            ull bb[8];
            bb[0] = bcast(b0.x); bb[1] = bcast(b0.y);
            bb[2] = bcast(b0.z); bb[3] = bcast(b0.w);
            bb[4] = bcast(b1.x); bb[5] = bcast(b1.y);
            bb[6] = bcast(b1.z); bb[7] = bcast(b1.w);
#pragma unroll
            for (int c = 0; c < 8; c++) {
                fma2(acc[c],      aA.x, bb[c]);
                fma2(acc[8 + c],  aA.y, bb[c]);
                fma2(acc[16 + c], aB.x, bb[c]);
                fma2(acc[24 + c], aB.y, bb[c]);
            }
        }
        __syncthreads();
    }

    // ---- epilogue: 4 row pairs x 8 cols ----
#pragma unroll
    for (int rp = 0; rp < 4; rp++) {
        long r = row0 + ty * 8 + rp * 2;
        float lo[8], hi[8];
#pragma unroll
        for (int c = 0; c < 8; c++) {
            ull av = acc[rp * 8 + c];
            float v0 = __uint_as_float((unsigned int)av) * alpha;
            float v1 = __uint_as_float((unsigned int)(av >> 32)) * alpha;
            if (act) {
                v0 = v0 / (1.f + __expf(-v0));
                v1 = v1 / (1.f + __expf(-v1));
            }
            lo[c] = v0; hi[c] = v1;
        }
        if (ccs == 1) {
            float* c0 = C + r * crs + col0 + tx * 8;
            float* c1 = c0 + crs;
            *(float4*)(c0)     = make_float4(lo[0], lo[1], lo[2], lo[3]);
            *(float4*)(c0 + 4) = make_float4(lo[4], lo[5], lo[6], lo[7]);
            *(float4*)(c1)     = make_float4(hi[0], hi[1], hi[2], hi[3]);
            *(float4*)(c1 + 4) = make_float4(hi[4], hi[5], hi[6], hi[7]);
        } else {
#pragma unroll
            for (int c = 0; c < 8; c++) {
                long col = (long)(col0 + tx * 8 + c) * ccs;
                C[r * crs + col] = lo[c];
                C[(r + 1) * crs + col] = hi[c];
            }
        }
    }
}

// ---------------- efm build ----------------
__global__ void k_efm(const float* __restrict__ EF, const float* __restrict__ MI,
                      const int* __restrict__ EI)
{
    int idx = blockIdx.x * 256 + threadIdx.x;     // E*16 threads
    int e = idx >> 4, k = idx & 15;
    float v;
    if (k < 8) v = EF[e * 8 + k];
    else       v = MI[(size_t)EI[e] * 8 + (k - 8)];
    g_EFM[idx] = v;
}

// ---------------- per-edge density ----------------
__global__ void k_dens(const float* __restrict__ EF, const float* __restrict__ DW)
{
    int e = blockIdx.x * 256 + threadIdx.x;       // E threads
    float d = 0.f;
#pragma unroll
    for (int i = 0; i < 8; i++) d += EF[e * 8 + i] * DW[i];
    d *= 0.3535533905932738f;                     // 1/sqrt(8)
    g_EDN[e] = tanhf(d * d);
}

// ---------------- counting sort by receiver ----------------
__global__ void k_zero()
{
    int i = blockIdx.x * 256 + threadIdx.x;
    if (i < N_NODES) { g_CNT[i] = 0; g_CUR[i] = 0; }
}
__global__ void k_hist(const int* __restrict__ EI)
{
    int e = blockIdx.x * 256 + threadIdx.x;
    atomicAdd(&g_CNT[EI[N_EDGES + e]], 1);
}
__global__ void k_scan()
{
    __shared__ int part[1024];
    int t = threadIdx.x;
    int loc[8]; int s = 0;
#pragma unroll
    for (int j = 0; j < 8; j++) { loc[j] = s; s += g_CNT[t * 8 + j]; }
    part[t] = s;
    __syncthreads();
    for (int off = 1; off < 1024; off <<= 1) {
        int v = (t >= off) ? part[t - off] : 0;
        __syncthreads();
        part[t] += v;
        __syncthreads();
    }
    int excl = part[t] - s;
#pragma unroll
    for (int j = 0; j < 8; j++) g_OFF[t * 8 + j] = excl + loc[j];
    if (t == 1023) g_OFF[N_NODES] = part[1023];
}
__global__ void k_scatter(const int* __restrict__ EI)
{
    int e = blockIdx.x * 256 + threadIdx.x;
    int r = EI[N_EDGES + e];
    int p = g_OFF[r] + atomicAdd(&g_CUR[r], 1);
    g_SORT[p] = e;
}

// ---------------- per-node edge combine + segment reduction (no atomics) ----------------
__global__ void __launch_bounds__(64) k_mm(const float* __restrict__ EA,
                                           const float* __restrict__ MA,
                                           const int* __restrict__ EI,
                                           const float* __restrict__ ATTR)
{
    const int n = blockIdx.x;
    const int u = threadIdx.x;
    const int beg = g_OFF[n], end = g_OFF[n + 1];

    float as0 = 0, as1 = 0, as2 = 0, as3 = 0, as4 = 0;
    float av[8][3];
#pragma unroll
    for (int j = 0; j < 8; j++)
#pragma unroll
        for (int i = 0; i < 3; i++) av[j][i] = 0.f;
    float dens = 0.f;

    const float I3 = 0.5773502691896258f;   // 1/sqrt(3)
    const float I2 = 0.7071067811865476f;   // 1/sqrt(2)

    for (int q = beg; q < end; q++) {
        const int e = g_SORT[q];
        const int snd = EI[e];
        const float* ea = EA + (size_t)e * 4;
        const float y0 = ea[0], yx = ea[1], yy = ea[2], yz = ea[3];
        const float* ma = MA + (size_t)snd * 4;
        const float m0 = ma[0], mx = ma[1], my = ma[2], mz = ma[3];
        const float xs = g_S[(size_t)snd * 64 + u];
        const float* vp = g_V + (size_t)snd * 192 + u;
        const float vx = vp[0], vy = vp[64], vz = vp[128];
        const float* tp = g_TP + (size_t)e * 320 + u;
        const float t0 = tp[0], t1 = tp[64], t2 = tp[128], t3 = tp[192], t4 = tp[256];
        const float* wm = g_WM + (size_t)e * 832 + u;

        const float ms0 = t0 * xs * y0;
        const float A0x = t1 * xs * yx, A0y = t1 * xs * yy, A0z = t1 * xs * yz;
        const float B0x = t2 * vx * y0, B0y = t2 * vy * y0, B0z = t2 * vz * y0;
        const float ms1 = t3 * (vx * yx + vy * yy + vz * yz) * I3;
        const float cx = vy * yz - vz * yy;
        const float cy = vz * yx - vx * yz;
        const float cz = vx * yy - vy * yx;
        const float C0x = t4 * cx * I2, C0y = t4 * cy * I2, C0z = t4 * cz * I2;

        as0 += wm[0] * ms0 * m0;
        { float w_ = wm[64] * ms0;  av[0][0] += w_ * mx; av[0][1] += w_ * my; av[0][2] += w_ * mz; }
        as1 += wm[128] * ms1 * m0;
        { float w_ = wm[192] * ms1; av[1][0] += w_ * mx; av[1][1] += w_ * my; av[1][2] += w_ * mz; }

        { float w_ = wm[256] * m0;  av[2][0] += w_ * A0x; av[2][1] += w_ * A0y; av[2][2] += w_ * A0z; }
        as2 += wm[320] * (A0x * mx + A0y * my + A0z * mz) * I3;
        { float w_ = wm[384] * I2;
          av[3][0] += w_ * (A0y * mz - A0z * my);
          av[3][1] += w_ * (A0z * mx - A0x * mz);
          av[3][2] += w_ * (A0x * my - A0y * mx); }

        { float w_ = wm[448] * m0;  av[4][0] += w_ * B0x; av[4][1] += w_ * B0y; av[4][2] += w_ * B0z; }
        as3 += wm[512] * (B0x * mx + B0y * my + B0z * mz) * I3;
        { float w_ = wm[576] * I2;
          av[5][0] += w_ * (B0y * mz - B0z * my);
          av[5][1] += w_ * (B0z * mx - B0x * mz);
          av[5][2] += w_ * (B0x * my - B0y * mx); }

        { float w_ = wm[640] * m0;  av[6][0] += w_ * C0x; av[6][1] += w_ * C0y; av[6][2] += w_ * C0z; }
        as4 += wm[704] * (C0x * mx + C0y * my + C0z * mz) * I3;
        { float w_ = wm[768] * I2;
          av[7][0] += w_ * (C0y * mz - C0z * my);
          av[7][1] += w_ * (C0z * mx - C0x * mz);
          av[7][2] += w_ * (C0x * my - C0y * mx); }

        dens += g_EDN[e];
    }

    const size_t b = (size_t)n * 320 + u;
    g_MS[b]       = as0;
    g_MS[b + 64]  = as1;
    g_MS[b + 128] = as2;
    g_MS[b + 192] = as3;
    g_MS[b + 256] = as4;
    const size_t bv = (size_t)n * 1536 + u;
#pragma unroll
    for (int i = 0; i < 3; i++)
#pragma unroll
        for (int j = 0; j < 8; j++)
            g_MV[bv + i * 512 + j * 64] = av[j][i];
    // attrs / (dens+1) for the fused skip GEMM (every thread holds the same dens)
    if (u < 10) g_AI[n * 10 + u] = ATTR[n * 10 + u] / (dens + 1.f);
}

// ---------------- launcher ----------------
extern "C" void kernel_launch(void* const* d_in, const int* in_sizes, int n_in,
                              void* d_out, int out_size)
{
    (void)in_sizes; (void)n_in; (void)out_size;
    const float* node_attrs = (const float*)d_in[0];
    const float* node_feats = (const float*)d_in[1];
    const float* edge_attrs = (const float*)d_in[2];
    const float* edge_feats = (const float*)d_in[3];
    const int*   edge_index = (const int*)  d_in[4];
    const float* maginv     = (const float*)d_in[5];
    const float* magattr    = (const float*)d_in[6];
    const float* Wups       = (const float*)d_in[7];
    const float* Wupv       = (const float*)d_in[8];
    const float* w0         = (const float*)d_in[9];
    const float* w1         = (const float*)d_in[10];
    const float* w2         = (const float*)d_in[11];
    const float* w3         = (const float*)d_in[12];
    const float* magw       = (const float*)d_in[13];
    const float* densw      = (const float*)d_in[14];
    const float* lins       = (const float*)d_in[15];
    const float* linv       = (const float*)d_in[16];
    const float* skips      = (const float*)d_in[17];
    const float* skipv      = (const float*)d_in[18];
    float* out = (float*)d_out;

    float *pS, *pV, *pEFM, *pHA, *pHB, *pTP, *pWM, *pMS, *pMV, *pMSP, *pMVP;
    cudaGetSymbolAddress((void**)&pS,   g_S);
    cudaGetSymbolAddress((void**)&pV,   g_V);
    cudaGetSymbolAddress((void**)&pEFM, g_EFM);
    cudaGetSymbolAddress((void**)&pHA,  g_HA);
    cudaGetSymbolAddress((void**)&pHB,  g_HB);
    cudaGetSymbolAddress((void**)&pTP,  g_TP);
    cudaGetSymbolAddress((void**)&pWM,  g_WM);
    cudaGetSymbolAddress((void**)&pMS,  g_MS);
    cudaGetSymbolAddress((void**)&pMV,  g_MV);
    cudaGetSymbolAddress((void**)&pMSP, g_MSP);
    cudaGetSymbolAddress((void**)&pMVP, g_MVP);

    const float a8   = 0.125f;                  // 1/sqrt(64)
    const float a4   = 0.25f;                   // 1/sqrt(16)
    const float a320 = 1.f / sqrtf(320.f);
    const float a512 = 1.f / sqrtf(512.f);
    const float a640 = 1.f / sqrtf(640.f);      // 1/fan

    const int NB = N_NODES / 128;   // 64
    const int EB = N_EDGES / 128;   // 512

    // node up-projection
    gemmk<false><<<dim3(NB, 1, 1), 128>>>(node_feats, 256, 1, 0, Wups, Wups, 64,
                                          pS, 64, 1, 0, 64, a8, 0, 0, 0);
    gemmk<false><<<dim3(NB, 1, 3), 128>>>(node_feats + 64, 256, 3, 1, Wupv, Wupv, 64,
                                          pV, 192, 1, 64, 64, a8, 0, 0, 0);

    // edge feature concat + density
    k_efm <<<N_EDGES*16/256, 256>>>(edge_feats, maginv, edge_index);
    k_dens<<<N_EDGES/256,    256>>>(edge_feats, densw);

    // edge MLP + mag projection
    gemmk<false><<<dim3(EB, 1,  1), 128>>>(pEFM, 16, 1, 0, w0,   w0,   64,  pHA, 64,  1, 0, 16, a4, 1, 0, 0);
    gemmk<false><<<dim3(EB, 1,  1), 128>>>(pHA,  64, 1, 0, w1,   w1,   64,  pHB, 64,  1, 0, 64, a8, 1, 0, 0);
    gemmk<false><<<dim3(EB, 1,  1), 128>>>(pHB,  64, 1, 0, w2,   w2,   64,  pHA, 64,  1, 0, 64, a8, 1, 0, 0);
    gemmk<false><<<dim3(EB, 5,  1), 128>>>(pHA,  64, 1, 0, w3,   w3,   320, pTP, 320, 1, 0, 64, a8, 0, 0, 0);
    gemmk<false><<<dim3(EB, 13, 1), 128>>>(pEFM, 16, 1, 0, magw, magw, 832, pWM, 832, 1, 0, 16, a4, 0, 0, 0);

    // counting sort of edges by receiver
    k_zero   <<<N_NODES/256, 256>>>();
    k_hist   <<<N_EDGES/256, 256>>>(edge_index);
    k_scan   <<<1, 1024>>>();
    k_scatter<<<N_EDGES/256, 256>>>(edge_index);

    // per-node tensor-product combine + segment reduction (+ g_AI)
    k_mm<<<N_NODES, 64>>>(edge_attrs, magattr, edge_index, node_attrs);

    // lin_s / lin_v
    gemmk<false><<<dim3(NB, 1, 1), 128>>>(pMS, 320, 1, 0, lins, lins, 64,
                                          pMSP, 64, 1, 0, 320, a320, 0, 0, 0);
    gemmk<false><<<dim3(NB, 1, 3), 128>>>(pMV, 1536, 1, 512, linv, linv, 64,
                                          pMVP, 192, 1, 64, 512, a512, 0, 0, 0);

    // skip einsum: coefficients built on the fly in A-staging (no g_C scratch)
    gemmk<true><<<dim3(NB, 1, 4), 128>>>(0, 0, 0, 0, skips, skipv, 64,
                                         out, 256, 4, 1, 640, a640, 0, pMSP, pMVP);
}

// round 4
// speedup vs baseline: 2.4463x; 1.0443x over previous
#include <cuda_runtime.h>
#include <math.h>

#define N_NODES 8192
#define N_EDGES 65536

typedef unsigned long long ull;

// ---------------- scratch (static device globals; no runtime alloc) ----------------
__device__ float g_S   [N_NODES*64];
__device__ float g_V   [N_NODES*192];
__device__ float g_EFM [(size_t)N_EDGES*16];
__device__ float g_EDN [N_EDGES];
__device__ float g_HA  [(size_t)N_EDGES*64];
__device__ float g_HB  [(size_t)N_EDGES*64];
__device__ float g_TP  [(size_t)N_EDGES*320];
__device__ float g_WM  [(size_t)N_EDGES*832];
__device__ float g_MS  [N_NODES*320];
__device__ float g_MV  [N_NODES*1536];
__device__ float g_AI  [N_NODES*10];          // attrs / (dens+1)
__device__ float g_MSP [N_NODES*64];
__device__ float g_MVP [N_NODES*192];
__device__ int   g_CNT [N_NODES];
__device__ int   g_CUR [N_NODES];
__device__ int   g_OFF [N_NODES+1];
__device__ int   g_SORT[N_EDGES];

__device__ __forceinline__ ull bcast(float f) {
    unsigned int u = __float_as_uint(f);
    ull r;
    asm("mov.b64 %0, {%1, %1};" : "=l"(r) : "r"(u));
    return r;
}
__device__ __forceinline__ void fma2(ull& acc, ull a, ull b) {
    asm("fma.rn.f32x2 %0, %1, %2, %0;" : "+l"(acc) : "l"(a), "l"(b));
}

// ================= register-blocked GEMM =================
// Tile: RB rows x 64 cols per block, 128 threads.
// RB=128: 8x8 microtile; RB=64: 4x8 microtile. Rows paired in f32x2.
// C[row, col, z] = act( alpha * sum_k A[z][row,k] * B[z][k,col] )
// Normal mode:  A element (n,k) = (A + z*azs)[n*ars + k*acs]
// SKIP mode (RB=128 only): A(n,k) = msel[n, k/10] * g_AI[n*10 + k%10],
//   msel = (z==0 ? MSP stride 64 : MVP + (z-1)*64, stride 192)
// B: z==0 -> B0, else Bz;  B[k*brs + col]
// C: (C + z*czs)[row*crs + col*ccs]
template<int RB, bool SKIP>
__global__ void __launch_bounds__(128) gemmk(
    const float* __restrict__ A, long ars, int acs, long azs,
    const float* __restrict__ B0, const float* __restrict__ Bz, int brs,
    float* __restrict__ C, long crs, int ccs, long czs,
    int K, float alpha, int act,
    const float* __restrict__ MSP, const float* __restrict__ MVP)
{
    const int LDA = RB + 4;
    const int RPT = RB / 16;       // rows per thread (8 or 4)
    const int PPT = RPT / 2;       // row pairs per thread (4 or 2)
    __shared__ float As[32*(RB+4)];   // [kk][row]
    __shared__ float Bs[32*68];       // [kk][col]

    const int tid = threadIdx.x;
    const int tx = tid & 7;        // col group (8 cols each)
    const int ty = tid >> 3;       // row group, 0..15
    const long row0 = (long)blockIdx.x * RB;
    const int  col0 = blockIdx.y * 64;
    const int  z = blockIdx.z;
    const float* __restrict__ B = (z == 0) ? B0 : Bz;
    C += (long)z * czs;

    // A staging ownership: thread owns row (tid % RB), k-segment (tid/RB)*16
    const int arow = tid & (RB - 1);
    const int kseg = (RB == 128) ? 0 : ((tid >> 6) * 16);
    const int KPT  = (RB == 128) ? 32 : 16;   // kks staged per thread

    const float* Arow;
    const float* ai = 0;
    if (SKIP) {
        Arow = (z == 0) ? (MSP + (row0 + arow) * 64)
                        : (MVP + (row0 + arow) * 192 + (z - 1) * 64);
        ai = g_AI + (row0 + arow) * 10;
    } else {
        Arow = A + (long)z * azs + (row0 + arow) * ars;
    }

    ull acc[PPT * 8];
#pragma unroll
    for (int i = 0; i < PPT * 8; i++) acc[i] = 0ull;

    for (int k0 = 0; k0 < K; k0 += 32) {
        // ---- stage A ----
        if (SKIP) {
#pragma unroll 8
            for (int c = 0; c < KPT; c++) {
                int k = k0 + kseg + c;            // K=640 exact -> no guard
                int u = (k * 6554) >> 16;
                int v = k - u * 10;
                As[(kseg + c) * LDA + arow] = Arow[u] * ai[v];
            }
        } else if (acs == 1) {
#pragma unroll
            for (int c = 0; c < KPT / 4; c++) {
                int kk = kseg + c * 4;
                float4 val = make_float4(0.f, 0.f, 0.f, 0.f);
                if (k0 + kk < K)
                    val = *(const float4*)(Arow + k0 + kk);
                As[(kk + 0) * LDA + arow] = val.x;
                As[(kk + 1) * LDA + arow] = val.y;
                As[(kk + 2) * LDA + arow] = val.z;
                As[(kk + 3) * LDA + arow] = val.w;
            }
        } else {
#pragma unroll 8
            for (int c = 0; c < KPT; c++) {
                int kk = kseg + c;
                float v = 0.f;
                if (k0 + kk < K) v = Arow[(long)(k0 + kk) * acs];
                As[kk * LDA + arow] = v;
            }
        }
        // ---- stage B ----
#pragma unroll
        for (int j = 0; j < 4; j++) {
            int kk = (tid >> 4) + j * 8;
            int c  = (tid & 15) * 4;
            float4 val = make_float4(0.f, 0.f, 0.f, 0.f);
            if (k0 + kk < K)
                val = *(const float4*)(B + (size_t)(k0 + kk) * brs + col0 + c);
            *(float4*)(Bs + kk * 68 + c) = val;
        }
        __syncthreads();

#pragma unroll 4
        for (int kk = 0; kk < 32; kk++) {
            ull ar[PPT];
            {
                const ulonglong2* ap = (const ulonglong2*)(As + kk * LDA + ty * RPT);
                ulonglong2 t0 = ap[0];
                ar[0] = t0.x; ar[1] = t0.y;
                if (RB == 128) {
                    ulonglong2 t1 = ap[1];
                    ar[2] = t1.x; ar[3] = t1.y;
                }
            }
            const float4* bp = (const float4*)(Bs + kk * 68 + tx * 8);
            float4 b0 = bp[0], b1 = bp[1];
            ull bb[8];
            bb[0] = bcast(b0.x); bb[1] = bcast(b0.y);
            bb[2] = bcast(b0.z); bb[3] = bcast(b0.w);
            bb[4] = bcast(b1.x); bb[5] = bcast(b1.y);
            bb[6] = bcast(b1.z); bb[7] = bcast(b1.w);
#pragma unroll
            for (int c = 0; c < 8; c++)
#pragma unroll
                for (int p = 0; p < PPT; p++)
                    fma2(acc[p * 8 + c], ar[p], bb[c]);
        }
        __syncthreads();
    }

    // ---- epilogue: PPT row pairs x 8 cols ----
#pragma unroll
    for (int rp = 0; rp < PPT; rp++) {
        long r = row0 + ty * RPT + rp * 2;
        float lo[8], hi[8];
#pragma unroll
        for (int c = 0; c < 8; c++) {
            ull av = acc[rp * 8 + c];
            float v0 = __uint_as_float((unsigned int)av) * alpha;
            float v1 = __uint_as_float((unsigned int)(av >> 32)) * alpha;
            if (act) {
                v0 = v0 / (1.f + __expf(-v0));
                v1 = v1 / (1.f + __expf(-v1));
            }
            lo[c] = v0; hi[c] = v1;
        }
        if (ccs == 1) {
            float* c0 = C + r * crs + col0 + tx * 8;
            float* c1 = c0 + crs;
            *(float4*)(c0)     = make_float4(lo[0], lo[1], lo[2], lo[3]);
            *(float4*)(c0 + 4) = make_float4(lo[4], lo[5], lo[6], lo[7]);
            *(float4*)(c1)     = make_float4(hi[0], hi[1], hi[2], hi[3]);
            *(float4*)(c1 + 4) = make_float4(hi[4], hi[5], hi[6], hi[7]);
        } else {
#pragma unroll
            for (int c = 0; c < 8; c++) {
                long col = (long)(col0 + tx * 8 + c) * ccs;
                C[r * crs + col] = lo[c];
                C[(r + 1) * crs + col] = hi[c];
            }
        }
    }
}

// ---------------- efm build ----------------
__global__ void k_efm(const float* __restrict__ EF, const float* __restrict__ MI,
                      const int* __restrict__ EI)
{
    int idx = blockIdx.x * 256 + threadIdx.x;     // E*16 threads
    int e = idx >> 4, k = idx & 15;
    float v;
    if (k < 8) v = EF[e * 8 + k];
    else       v = MI[(size_t)EI[e] * 8 + (k - 8)];
    g_EFM[idx] = v;
}

// ---------------- counting sort by receiver (hist fused with density) ----------------
__global__ void k_zero()
{
    int i = blockIdx.x * 256 + threadIdx.x;
    if (i < N_NODES) { g_CNT[i] = 0; g_CUR[i] = 0; }
}
__global__ void k_hist(const int* __restrict__ EI, const float* __restrict__ EF,
                       const float* __restrict__ DW)
{
    int e = blockIdx.x * 256 + threadIdx.x;
    atomicAdd(&g_CNT[EI[N_EDGES + e]], 1);
    float d = 0.f;
#pragma unroll
    for (int i = 0; i < 8; i++) d += EF[e * 8 + i] * DW[i];
    d *= 0.3535533905932738f;                     // 1/sqrt(8)
    g_EDN[e] = tanhf(d * d);
}
__global__ void k_scan()
{
    __shared__ int part[1024];
    int t = threadIdx.x;
    int loc[8]; int s = 0;
#pragma unroll
    for (int j = 0; j < 8; j++) { loc[j] = s; s += g_CNT[t * 8 + j]; }
    part[t] = s;
    __syncthreads();
    for (int off = 1; off < 1024; off <<= 1) {
        int v = (t >= off) ? part[t - off] : 0;
        __syncthreads();
        part[t] += v;
        __syncthreads();
    }
    int excl = part[t] - s;
#pragma unroll
    for (int j = 0; j < 8; j++) g_OFF[t * 8 + j] = excl + loc[j];
    if (t == 1023) g_OFF[N_NODES] = part[1023];
}
__global__ void k_scatter(const int* __restrict__ EI)
{
    int e = blockIdx.x * 256 + threadIdx.x;
    int r = EI[N_EDGES + e];
    int p = g_OFF[r] + atomicAdd(&g_CUR[r], 1);
    g_SORT[p] = e;
}

// ---------------- per-node edge combine + segment reduction (no atomics) ----------------
__global__ void __launch_bounds__(64) k_mm(const float* __restrict__ EA,
                                           const float* __restrict__ MA,
                                           const int* __restrict__ EI,
                                           const float* __restrict__ ATTR)
{
    const int n = blockIdx.x;
    const int u = threadIdx.x;
    const int beg = g_OFF[n], end = g_OFF[n + 1];

    float as0 = 0, as1 = 0, as2 = 0, as3 = 0, as4 = 0;
    float av[8][3];
#pragma unroll
    for (int j = 0; j < 8; j++)
#pragma unroll
        for (int i = 0; i < 3; i++) av[j][i] = 0.f;
    float dens = 0.f;

    const float I3 = 0.5773502691896258f;   // 1/sqrt(3)
    const float I2 = 0.7071067811865476f;   // 1/sqrt(2)

    // prefetched next-edge indices break the dependent-load chain
    int e_nx = 0, s_nx = 0;
    if (beg < end) { e_nx = g_SORT[beg]; s_nx = EI[e_nx]; }

    for (int q = beg; q < end; q++) {
        const int e = e_nx, snd = s_nx;
        if (q + 1 < end) { e_nx = g_SORT[q + 1]; s_nx = EI[e_nx]; }

        const float4 eav = *(const float4*)(EA + (size_t)e * 4);
        const float y0 = eav.x, yx = eav.y, yy = eav.z, yz = eav.w;
        const float4 mav = *(const float4*)(MA + (size_t)snd * 4);
        const float m0 = mav.x, mx = mav.y, my = mav.z, mz = mav.w;
        const float xs = g_S[(size_t)snd * 64 + u];
        const float* vp = g_V + (size_t)snd * 192 + u;
        const float vx = vp[0], vy = vp[64], vz = vp[128];
        const float* tp = g_TP + (size_t)e * 320 + u;
        const float t0 = tp[0], t1 = tp[64], t2 = tp[128], t3 = tp[192], t4 = tp[256];
        const float* wm = g_WM + (size_t)e * 832 + u;

        const float ms0 = t0 * xs * y0;
        const float A0x = t1 * xs * yx, A0y = t1 * xs * yy, A0z = t1 * xs * yz;
        const float B0x = t2 * vx * y0, B0y = t2 * vy * y0, B0z = t2 * vz * y0;
        const float ms1 = t3 * (vx * yx + vy * yy + vz * yz) * I3;
        const float cx = vy * yz - vz * yy;
        const float cy = vz * yx - vx * yz;
        const float cz = vx * yy - vy * yx;
        const float C0x = t4 * cx * I2, C0y = t4 * cy * I2, C0z = t4 * cz * I2;

        as0 += wm[0] * ms0 * m0;
        { float w_ = wm[64] * ms0;  av[0][0] += w_ * mx; av[0][1] += w_ * my; av[0][2] += w_ * mz; }
        as1 += wm[128] * ms1 * m0;
        { float w_ = wm[192] * ms1; av[1][0] += w_ * mx; av[1][1] += w_ * my; av[1][2] += w_ * mz; }

        { float w_ = wm[256] * m0;  av[2][0] += w_ * A0x; av[2][1] += w_ * A0y; av[2][2] += w_ * A0z; }
        as2 += wm[320] * (A0x * mx + A0y * my + A0z * mz) * I3;
        { float w_ = wm[384] * I2;
          av[3][0] += w_ * (A0y * mz - A0z * my);
          av[3][1] += w_ * (A0z * mx - A0x * mz);
          av[3][2] += w_ * (A0x * my - A0y * mx); }

        { float w_ = wm[448] * m0;  av[4][0] += w_ * B0x; av[4][1] += w_ * B0y; av[4][2] += w_ * B0z; }
        as3 += wm[512] * (B0x * mx + B0y * my + B0z * mz) * I3;
        { float w_ = wm[576] * I2;
          av[5][0] += w_ * (B0y * mz - B0z * my);
          av[5][1] += w_ * (B0z * mx - B0x * mz);
          av[5][2] += w_ * (B0x * my - B0y * mx); }

        { float w_ = wm[640] * m0;  av[6][0] += w_ * C0x; av[6][1] += w_ * C0y; av[6][2] += w_ * C0z; }
        as4 += wm[704] * (C0x * mx + C0y * my + C0z * mz) * I3;
        { float w_ = wm[768] * I2;
          av[7][0] += w_ * (C0y * mz - C0z * my);
          av[7][1] += w_ * (C0z * mx - C0x * mz);
          av[7][2] += w_ * (C0x * my - C0y * mx); }

        dens += g_EDN[e];
    }

    const size_t b = (size_t)n * 320 + u;
    g_MS[b]       = as0;
    g_MS[b + 64]  = as1;
    g_MS[b + 128] = as2;
    g_MS[b + 192] = as3;
    g_MS[b + 256] = as4;
    const size_t bv = (size_t)n * 1536 + u;
#pragma unroll
    for (int i = 0; i < 3; i++)
#pragma unroll
        for (int j = 0; j < 8; j++)
            g_MV[bv + i * 512 + j * 64] = av[j][i];
    if (u < 10) g_AI[n * 10 + u] = ATTR[n * 10 + u] / (dens + 1.f);
}

// ---------------- launcher ----------------
extern "C" void kernel_launch(void* const* d_in, const int* in_sizes, int n_in,
                              void* d_out, int out_size)
{
    (void)in_sizes; (void)n_in; (void)out_size;
    const float* node_attrs = (const float*)d_in[0];
    const float* node_feats = (const float*)d_in[1];
    const float* edge_attrs = (const float*)d_in[2];
    const float* edge_feats = (const float*)d_in[3];
    const int*   edge_index = (const int*)  d_in[4];
    const float* maginv     = (const float*)d_in[5];
    const float* magattr    = (const float*)d_in[6];
    const float* Wups       = (const float*)d_in[7];
    const float* Wupv       = (const float*)d_in[8];
    const float* w0         = (const float*)d_in[9];
    const float* w1         = (const float*)d_in[10];
    const float* w2         = (const float*)d_in[11];
    const float* w3         = (const float*)d_in[12];
    const float* magw       = (const float*)d_in[13];
    const float* densw      = (const float*)d_in[14];
    const float* lins       = (const float*)d_in[15];
    const float* linv       = (const float*)d_in[16];
    const float* skips      = (const float*)d_in[17];
    const float* skipv      = (const float*)d_in[18];
    float* out = (float*)d_out;

    float *pS, *pV, *pEFM, *pHA, *pHB, *pTP, *pWM, *pMS, *pMV, *pMSP, *pMVP;
    cudaGetSymbolAddress((void**)&pS,   g_S);
    cudaGetSymbolAddress((void**)&pV,   g_V);
    cudaGetSymbolAddress((void**)&pEFM, g_EFM);
    cudaGetSymbolAddress((void**)&pHA,  g_HA);
    cudaGetSymbolAddress((void**)&pHB,  g_HB);
    cudaGetSymbolAddress((void**)&pTP,  g_TP);
    cudaGetSymbolAddress((void**)&pWM,  g_WM);
    cudaGetSymbolAddress((void**)&pMS,  g_MS);
    cudaGetSymbolAddress((void**)&pMV,  g_MV);
    cudaGetSymbolAddress((void**)&pMSP, g_MSP);
    cudaGetSymbolAddress((void**)&pMVP, g_MVP);

    const float a8   = 0.125f;                  // 1/sqrt(64)
    const float a4   = 0.25f;                   // 1/sqrt(16)
    const float a320 = 1.f / sqrtf(320.f);
    const float a512 = 1.f / sqrtf(512.f);
    const float a640 = 1.f / sqrtf(640.f);      // 1/fan

    const int EB = N_EDGES / 128;   // 512

    // --- edge path first (slot 3 = magw GEMM for ncu) ---
    k_efm<<<N_EDGES*16/256, 256>>>(edge_feats, maginv, edge_index);                           // 0
    gemmk<128,false><<<dim3(EB, 1,  1), 128>>>(pEFM, 16, 1, 0, w0, w0, 64,
                                               pHA, 64, 1, 0, 16, a4, 1, 0, 0);              // 1
    gemmk<128,false><<<dim3(EB, 1,  1), 128>>>(pHA, 64, 1, 0, w1, w1, 64,
                                               pHB, 64, 1, 0, 64, a8, 1, 0, 0);              // 2
    gemmk<128,false><<<dim3(EB, 13, 1), 128>>>(pEFM, 16, 1, 0, magw, magw, 832,
                                               pWM, 832, 1, 0, 16, a4, 0, 0, 0);             // 3 (profiled)
    gemmk<128,false><<<dim3(EB, 1,  1), 128>>>(pHB, 64, 1, 0, w2, w2, 64,
                                               pHA, 64, 1, 0, 64, a8, 1, 0, 0);              // 4
    gemmk<128,false><<<dim3(EB, 5,  1), 128>>>(pHA, 64, 1, 0, w3, w3, 320,
                                               pTP, 320, 1, 0, 64, a8, 0, 0, 0);             // 5

    // node up-projection (RB=64 -> 2x grid)
    gemmk<64,false><<<dim3(N_NODES/64, 1, 1), 128>>>(node_feats, 256, 1, 0, Wups, Wups, 64,
                                                     pS, 64, 1, 0, 64, a8, 0, 0, 0);
    gemmk<64,false><<<dim3(N_NODES/64, 1, 3), 128>>>(node_feats + 64, 256, 3, 1, Wupv, Wupv, 64,
                                                     pV, 192, 1, 64, 64, a8, 0, 0, 0);

    // counting sort of edges by receiver (hist fused with density)
    k_zero   <<<N_NODES/256, 256>>>();
    k_hist   <<<N_EDGES/256, 256>>>(edge_index, edge_feats, densw);
    k_scan   <<<1, 1024>>>();
    k_scatter<<<N_EDGES/256, 256>>>(edge_index);

    // per-node tensor-product combine + segment reduction (+ g_AI)
    k_mm<<<N_NODES, 64>>>(edge_attrs, magattr, edge_index, node_attrs);

    // lin_s / lin_v (RB=64 -> 2x grid)
    gemmk<64,false><<<dim3(N_NODES/64, 1, 1), 128>>>(pMS, 320, 1, 0, lins, lins, 64,
                                                     pMSP, 64, 1, 0, 320, a320, 0, 0, 0);
    gemmk<64,false><<<dim3(N_NODES/64, 1, 3), 128>>>(pMV, 1536, 1, 512, linv, linv, 64,
                                                     pMVP, 192, 1, 64, 512, a512, 0, 0, 0);

    // skip einsum: coefficients built on the fly in A-staging
    gemmk<128,true><<<dim3(N_NODES/128, 1, 4), 128>>>(0, 0, 0, 0, skips, skipv, 64,
                                                      out, 256, 4, 1, 640, a640, 0, pMSP, pMVP);
}